// round 16
// baseline (speedup 1.0000x reference)
#include <cuda_runtime.h>
#include <cuda_bf16.h>
#include <math.h>
#include <stdint.h>

// ---------------- problem constants ----------------
#define BATCH   2
#define CMODEL  96
#define LSEQ    4096
#define BB      8
#define DIN     192
#define DSTATE  128
#define CONVD   448
#define NH      3
#define HD      64
#define NPROJ   643
#define NPROJ_S 644
#define CHUNK   256
#define NC      16
#define MROWS   (BB*LSEQ)       // 32768

// ---------------- scratch (16B-aligned bf16 buffers) ----------------
__device__ __align__(16) __nv_bfloat16 g_xs[MROWS * CMODEL];
__device__ __align__(16) __nv_bfloat16 g_zxbcdt[MROWS * NPROJ_S];
__device__ float g_dtraw[MROWS * NH];
__device__ __align__(16) __nv_bfloat16 g_xBC[MROWS * CONVD];
__device__ float g_dt[MROWS * NH];
__device__ float g_dAc[MROWS * NH];
__device__ __align__(16) __nv_bfloat16 g_y[MROWS * DIN];
__device__ __align__(16) __nv_bfloat16 g_ysd[MROWS * CMODEL];
__device__ float g_states[BB * NC * NH * HD * DSTATE];
__device__ float g_prev[BB * NC * NH * HD * DSTATE];

// ---------------- mma helpers ----------------
__device__ __forceinline__ uint32_t f2tf(float f) {
    uint32_t u;
    asm("cvt.rna.tf32.f32 %0, %1;" : "=r"(u) : "f"(f));
    return u;
}
__device__ __forceinline__ void mma_tf32(float c[4], uint32_t a0, uint32_t a1, uint32_t a2, uint32_t a3,
                                         uint32_t b0, uint32_t b1) {
    asm volatile("mma.sync.aligned.m16n8k8.row.col.f32.tf32.tf32.f32 "
                 "{%0,%1,%2,%3}, {%4,%5,%6,%7}, {%8,%9}, {%0,%1,%2,%3};"
                 : "+f"(c[0]), "+f"(c[1]), "+f"(c[2]), "+f"(c[3])
                 : "r"(a0), "r"(a1), "r"(a2), "r"(a3), "r"(b0), "r"(b1));
}
__device__ __forceinline__ void mma_bf16(float c[4], uint32_t a0, uint32_t a1, uint32_t a2, uint32_t a3,
                                         uint32_t b0, uint32_t b1) {
    asm volatile("mma.sync.aligned.m16n8k16.row.col.f32.bf16.bf16.f32 "
                 "{%0,%1,%2,%3}, {%4,%5,%6,%7}, {%8,%9}, {%0,%1,%2,%3};"
                 : "+f"(c[0]), "+f"(c[1]), "+f"(c[2]), "+f"(c[3])
                 : "r"(a0), "r"(a1), "r"(a2), "r"(a3), "r"(b0), "r"(b1));
}
#define BF_LO(u) ((u) << 16)
#define BF_HI(u) ((u) & 0xFFFF0000u)
__device__ __forceinline__ uint32_t packbf(float a, float b) {
    union { __nv_bfloat162 h2; uint32_t u; } p;
    p.h2 = __floats2bfloat162_rn(a, b);
    return p.u;
}
__device__ __forceinline__ float blo(uint32_t u) { return __uint_as_float(BF_LO(u)); }
__device__ __forceinline__ float bhi(uint32_t u) { return __uint_as_float(BF_HI(u)); }

// ============ kernel 1: rmsnorm + cross-scan -> bf16 (16-pixel tiles) ============
__global__ void k_rms_scan(const float* __restrict__ x, const float* __restrict__ norm_w) {
    __shared__ float sx[96][17];
    __shared__ float rs[16];
    __shared__ float wsh[96];
    int bi = blockIdx.x >> 8;
    int l0 = (blockIdx.x & 255) * 16;
    int tid = threadIdx.x;                 // 256
    if (tid < 96) wsh[tid] = norm_w[tid];
    for (int i = tid; i < 96 * 16; i += 256) {
        int ch = i >> 4, ll = i & 15;
        sx[ch][ll] = x[((bi * 96 + ch) << 12) + l0 + ll];
    }
    __syncthreads();
    if (tid < 16) {
        float ssum = 0.f;
        #pragma unroll 8
        for (int ch = 0; ch < 96; ch++) { float v = sx[ch][tid]; ssum = fmaf(v, v, ssum); }
        rs[tid] = rsqrtf(ssum / 96.0f + 1.1920929e-07f);
    }
    __syncthreads();
    for (int i = tid; i < 768; i += 256) {
        int ll = i / 48, cp = i - ll * 48;
        int ch = cp * 2;
        int l = l0 + ll;
        float r = rs[ll];
        float nv0 = sx[ch][ll] * r * wsh[ch];
        float nv1 = sx[ch + 1][ll] * r * wsh[ch + 1];
        __nv_bfloat162 pk = __floats2bfloat162_rn(nv0, nv1);
        int hh = l >> 6, ww = l & 63;
        int lt = (ww << 6) + hh;
        *(__nv_bfloat162*)&g_xs[((((bi * 4 + 0) << 12) + l) * 96) + ch] = pk;
        *(__nv_bfloat162*)&g_xs[((((bi * 4 + 1) << 12) + (4095 - l)) * 96) + ch] = pk;
        *(__nv_bfloat162*)&g_xs[((((bi * 4 + 2) << 12) + lt) * 96) + ch] = pk;
        *(__nv_bfloat162*)&g_xs[((((bi * 4 + 3) << 12) + (4095 - lt)) * 96) + ch] = pk;
    }
}

// ============ kernel 2: in_proj GEMM via bf16 MMA (M=32768, N=643, K=96) ============
__global__ void k_inproj_mma(const float* __restrict__ W) {
    extern __shared__ uint32_t ipm[];
    uint32_t (*As)[52] = (uint32_t(*)[52])ipm;
    uint32_t (*Bs)[52] = (uint32_t(*)[52])(ipm + 128 * 52);
    int bm = blockIdx.y * 128;
    int bn = blockIdx.x * 128;
    int tid = threadIdx.x;
    int lane = tid & 31, wid = tid >> 5;
    int wm = (wid & 1) * 64;
    int wn = (wid >> 1) * 32;
    for (int i = tid; i < 128 * 12; i += 256) {
        int r = i / 12, q = i - r * 12;
        uint4 raw = *(const uint4*)&g_xs[(bm + r) * CMODEL + q * 8];
        *(uint4*)&As[r][q * 4] = raw;
    }
    for (int i = tid; i < 128 * 24; i += 256) {
        int r = i / 24, q = i - r * 24;
        int n = bn + r;
        float4 v = make_float4(0.f, 0.f, 0.f, 0.f);
        if (n < NPROJ) v = *(const float4*)&W[n * CMODEL + q * 4];
        Bs[r][q * 2]     = packbf(v.x, v.y);
        Bs[r][q * 2 + 1] = packbf(v.z, v.w);
    }
    __syncthreads();
    float acc[4][4][4] = {};
    #pragma unroll
    for (int k16 = 0; k16 < 6; k16++) {
        int kp = k16 * 8 + (lane & 3);
        uint32_t af[4][4], bf[4][2];
        int rA = lane >> 2;
        #pragma unroll
        for (int mi = 0; mi < 4; mi++) {
            int r = wm + mi * 16 + rA;
            af[mi][0] = As[r][kp];     af[mi][1] = As[r + 8][kp];
            af[mi][2] = As[r][kp + 4]; af[mi][3] = As[r + 8][kp + 4];
        }
        #pragma unroll
        for (int ni = 0; ni < 4; ni++) {
            int cn = wn + ni * 8 + rA;
            bf[ni][0] = Bs[cn][kp];
            bf[ni][1] = Bs[cn][kp + 4];
        }
        #pragma unroll
        for (int mi = 0; mi < 4; mi++)
            #pragma unroll
            for (int ni = 0; ni < 4; ni++)
                mma_bf16(acc[mi][ni], af[mi][0], af[mi][1], af[mi][2], af[mi][3],
                         bf[ni][0], bf[ni][1]);
    }
    int gid = lane >> 2, tig = lane & 3;
    #pragma unroll
    for (int mi = 0; mi < 4; mi++) {
        int r0 = bm + wm + mi * 16 + gid;
        #pragma unroll
        for (int ni = 0; ni < 4; ni++) {
            int c0 = bn + wn + ni * 8 + tig * 2;
            float a0 = acc[mi][ni][0], a1 = acc[mi][ni][1];
            float a2 = acc[mi][ni][2], a3 = acc[mi][ni][3];
            if (c0 + 1 < NPROJ) {
                *(__nv_bfloat162*)&g_zxbcdt[r0 * NPROJ_S + c0]       = __floats2bfloat162_rn(a0, a1);
                *(__nv_bfloat162*)&g_zxbcdt[(r0 + 8) * NPROJ_S + c0] = __floats2bfloat162_rn(a2, a3);
            } else if (c0 < NPROJ) {
                g_zxbcdt[r0 * NPROJ_S + c0]       = __float2bfloat16(a0);
                g_zxbcdt[(r0 + 8) * NPROJ_S + c0] = __float2bfloat16(a2);
            }
            int hh0 = c0 - (DIN + CONVD);
            if (hh0 >= 0 && hh0 < NH) {
                g_dtraw[r0 * NH + hh0] = a0;
                g_dtraw[(r0 + 8) * NH + hh0] = a2;
            }
            if (hh0 + 1 >= 0 && hh0 + 1 < NH) {
                g_dtraw[r0 * NH + hh0 + 1] = a1;
                g_dtraw[(r0 + 8) * NH + hh0 + 1] = a3;
            }
        }
    }
}
#define SMEM_INPROJ (2 * 128 * 52 * 4)

// ============ kernel 3: dt softplus + per-chunk cumsum ============
__global__ void k_dt(const float* __restrict__ dt_bias, const float* __restrict__ A_log) {
    int cb = blockIdx.x;
    int t  = threadIdx.x;                 // 256
    int m  = cb * CHUNK + t;
    int lane = t & 31, wid = t >> 5;
    __shared__ float wsum[8], woff[8];
    for (int h = 0; h < NH; h++) {
        float raw = g_dtraw[m * NH + h] + dt_bias[h];
        float dtv = (raw > 20.0f) ? raw : log1pf(expf(raw));
        g_dt[m * NH + h] = dtv;
        float Ah = -expf(A_log[h]);
        float s = dtv * Ah;
        #pragma unroll
        for (int o = 1; o < 32; o <<= 1) {
            float n = __shfl_up_sync(0xffffffffu, s, o);
            if (lane >= o) s += n;
        }
        if (lane == 31) wsum[wid] = s;
        __syncthreads();
        if (t < 8) {
            float ws = wsum[t];
            #pragma unroll
            for (int o = 1; o < 8; o <<= 1) {
                float n = __shfl_up_sync(0xffu, ws, o);
                if (t >= o) ws += n;
            }
            woff[t] = ws;
        }
        __syncthreads();
        float off = wid ? woff[wid - 1] : 0.0f;
        g_dAc[m * NH + h] = s + off;
        __syncthreads();
    }
}

// ============ kernel 4: depthwise causal conv + SiLU, smem-tiled ============
// block: 32 output rows x 448 ch; 224 thr; tile rows base-3..base+31 staged in smem
__global__ void k_conv(const float* __restrict__ cw, const float* __restrict__ cb) {
    __shared__ uint2 sd[35][112];          // 35 rows x 448 bf16 (uint2 = 4 ch)
    int tid = threadIdx.x;                 // 224
    int base = blockIdx.x * 32;
    bool seqstart = ((base & 4095) == 0);
    const __nv_bfloat16* srcrow = g_zxbcdt + DIN;
    for (int i = tid; i < 35 * 112; i += 224) {
        int row = i / 112, qq = i - row * 112;
        uint2 v = make_uint2(0u, 0u);
        if (!(seqstart && row < 3))
            v = *(const uint2*)&srcrow[(size_t)(base - 3 + row) * NPROJ_S + qq * 4];
        sd[row][qq] = v;
    }
    int q = tid % 112, rh = tid / 112;     // rh in {0,1}: 16 rows each
    int c4 = q * 4;
    float4 w0 = *(const float4*)&cw[(c4 + 0) * 4];
    float4 w1 = *(const float4*)&cw[(c4 + 1) * 4];
    float4 w2 = *(const float4*)&cw[(c4 + 2) * 4];
    float4 w3 = *(const float4*)&cw[(c4 + 3) * 4];
    float4 bias = *(const float4*)&cb[c4];
    __syncthreads();
    int r0w = rh * 16;
    uint2 u0 = sd[r0w + 0][q];
    uint2 u1 = sd[r0w + 1][q];
    uint2 u2 = sd[r0w + 2][q];
    #pragma unroll 4
    for (int r = 0; r < 16; r++) {
        uint2 u3 = sd[r0w + r + 3][q];
        float a0 = bias.x + w0.x * blo(u0.x) + w0.y * blo(u1.x) + w0.z * blo(u2.x) + w0.w * blo(u3.x);
        float a1 = bias.y + w1.x * bhi(u0.x) + w1.y * bhi(u1.x) + w1.z * bhi(u2.x) + w1.w * bhi(u3.x);
        float a2 = bias.z + w2.x * blo(u0.y) + w2.y * blo(u1.y) + w2.z * blo(u2.y) + w2.w * blo(u3.y);
        float a3 = bias.w + w3.x * bhi(u0.y) + w3.y * bhi(u1.y) + w3.z * bhi(u2.y) + w3.w * bhi(u3.y);
        float o0 = a0 / (1.0f + __expf(-a0));
        float o1 = a1 / (1.0f + __expf(-a1));
        float o2 = a2 / (1.0f + __expf(-a2));
        float o3 = a3 / (1.0f + __expf(-a3));
        uint2 pk;
        pk.x = packbf(o0, o1);
        pk.y = packbf(o2, o3);
        *(uint2*)&g_xBC[(size_t)(base + r0w + r) * CONVD + c4] = pk;
        u0 = u1; u1 = u2; u2 = u3;
    }
}

// ============ kernel 5: intra-chunk SSD; GEMM1 & GEMM2 bf16 MMA ============
__global__ void k_intra_mma(const float* __restrict__ Dp) {
    extern __shared__ uint32_t smb[];
    uint32_t (*Cs)[68]  = (uint32_t(*)[68])smb;
    uint32_t (*Bs)[68]  = (uint32_t(*)[68])(smb + 64 * 68);
    uint32_t (*XsT)[33] = (uint32_t(*)[33])(smb + 2 * 64 * 68);
    uint32_t (*Ssm)[33] = (uint32_t(*)[33])Bs;
    float* dAs = (float*)(smb + 2 * 64 * 68 + 64 * 33);
    float* dAt = dAs + 64;
    float* dtt = dAt + 64;

    int bx = blockIdx.x;
    int st = 3 - (bx & 3);
    int rest = bx >> 2;
    int h = rest % 3; rest /= 3;
    int c = rest & 15;
    int bb = rest >> 4;
    int m0 = bb * LSEQ + c * CHUNK;
    int tid = threadIdx.x, lane = tid & 31, wid = tid >> 5;

    int sbase = m0 + st * 64;
    for (int i = tid; i < 64 * 16; i += 128) {
        int r = i >> 4, q = i & 15;
        uint4 raw = *(const uint4*)&g_xBC[(sbase + r) * CONVD + (DIN + DSTATE) + q * 8];
        *(uint4*)&Cs[r][q * 4] = raw;
    }
    if (tid < 64) dAs[tid] = g_dAc[(sbase + tid) * NH + h];

    float accY[8][4] = {};

    for (int tt = 0; tt <= st; tt++) {
        int tbase = m0 + tt * 64;
        __syncthreads();
        for (int i = tid; i < 64 * 16; i += 128) {
            int r = i >> 4, q = i & 15;
            uint4 raw = *(const uint4*)&g_xBC[(tbase + r) * CONVD + DIN + q * 8];
            *(uint4*)&Bs[r][q * 4] = raw;
        }
        for (int i = tid; i < 32 * 16; i += 128) {
            int tp = i >> 4, p4 = (i & 15) * 4;
            uint2 e = *(const uint2*)&g_xBC[(tbase + 2 * tp)     * CONVD + h * HD + p4];
            uint2 o = *(const uint2*)&g_xBC[(tbase + 2 * tp + 1) * CONVD + h * HD + p4];
            XsT[p4 + 0][tp] = (e.x & 0xFFFFu)  | (o.x << 16);
            XsT[p4 + 1][tp] = (e.x >> 16)      | (o.x & 0xFFFF0000u);
            XsT[p4 + 2][tp] = (e.y & 0xFFFFu)  | (o.y << 16);
            XsT[p4 + 3][tp] = (e.y >> 16)      | (o.y & 0xFFFF0000u);
        }
        if (tid < 64) {
            dAt[tid] = g_dAc[(tbase + tid) * NH + h];
            dtt[tid] = g_dt[(tbase + tid) * NH + h];
        }
        __syncthreads();

        float S[8][4] = {};
        #pragma unroll
        for (int k16 = 0; k16 < 8; k16++) {
            int rA = wid * 16 + (lane >> 2);
            int kp = k16 * 8 + (lane & 3);
            uint32_t a0 = Cs[rA][kp],     a1 = Cs[rA + 8][kp];
            uint32_t a2 = Cs[rA][kp + 4], a3 = Cs[rA + 8][kp + 4];
            #pragma unroll
            for (int nf = 0; nf < 8; nf++) {
                int t = nf * 8 + (lane >> 2);
                mma_bf16(S[nf], a0, a1, a2, a3, Bs[t][kp], Bs[t][kp + 4]);
            }
        }
        __syncthreads();
        {
            int gid = lane >> 2, tig = lane & 3;
            #pragma unroll
            for (int nf = 0; nf < 8; nf++) {
                int tl = nf * 8 + tig * 2;
                int sl = wid * 16 + gid;
                bool ok0 = (tt < st) || (tl     <= sl);
                bool ok1 = (tt < st) || (tl + 1 <= sl);
                bool ok2 = (tt < st) || (tl     <= sl + 8);
                bool ok3 = (tt < st) || (tl + 1 <= sl + 8);
                float f0 = ok0 ? __expf(dAs[sl]     - dAt[tl])     * dtt[tl]     : 0.0f;
                float f1 = ok1 ? __expf(dAs[sl]     - dAt[tl + 1]) * dtt[tl + 1] : 0.0f;
                float f2 = ok2 ? __expf(dAs[sl + 8] - dAt[tl])     * dtt[tl]     : 0.0f;
                float f3 = ok3 ? __expf(dAs[sl + 8] - dAt[tl + 1]) * dtt[tl + 1] : 0.0f;
                Ssm[sl][nf * 4 + tig]     = packbf(S[nf][0] * f0, S[nf][1] * f1);
                Ssm[sl + 8][nf * 4 + tig] = packbf(S[nf][2] * f2, S[nf][3] * f3);
            }
        }
        __syncthreads();
        #pragma unroll
        for (int k16 = 0; k16 < 4; k16++) {
            int rA = wid * 16 + (lane >> 2);
            int kp = k16 * 8 + (lane & 3);
            uint32_t a0 = Ssm[rA][kp],     a1 = Ssm[rA + 8][kp];
            uint32_t a2 = Ssm[rA][kp + 4], a3 = Ssm[rA + 8][kp + 4];
            #pragma unroll
            for (int nf = 0; nf < 8; nf++) {
                int pn = nf * 8 + (lane >> 2);
                mma_bf16(accY[nf], a0, a1, a2, a3, XsT[pn][kp], XsT[pn][kp + 4]);
            }
        }
    }
    float Dh = Dp[h];
    int gid = lane >> 2, tig = lane & 3;
    #pragma unroll
    for (int nf = 0; nf < 8; nf++) {
        int sl = wid * 16 + gid;
        int s = st * 64 + sl;
        int p = nf * 8 + tig * 2;
        bool odd = (sl & 1);
        uint32_t ua = XsT[p][sl >> 1],       ub = XsT[p + 1][sl >> 1];
        uint32_t uc = XsT[p][(sl + 8) >> 1], ud = XsT[p + 1][(sl + 8) >> 1];
        float x00 = __uint_as_float(odd ? BF_HI(ua) : BF_LO(ua));
        float x01 = __uint_as_float(odd ? BF_HI(ub) : BF_LO(ub));
        float x10 = __uint_as_float(odd ? BF_HI(uc) : BF_LO(uc));
        float x11 = __uint_as_float(odd ? BF_HI(ud) : BF_LO(ud));
        *(__nv_bfloat162*)&g_y[(m0 + s) * DIN + h * HD + p] =
            __floats2bfloat162_rn(accY[nf][0] + Dh * x00, accY[nf][1] + Dh * x01);
        *(__nv_bfloat162*)&g_y[(m0 + s + 8) * DIN + h * HD + p] =
            __floats2bfloat162_rn(accY[nf][2] + Dh * x10, accY[nf][3] + Dh * x11);
    }
}
#define SMEM_INTRA ((2 * 64 * 68 + 64 * 33 + 3 * 64) * 4)

// ============ kernel 6: per-chunk end states via tf32 MMA ============
__global__ void k_states() {
    __shared__ uint32_t Xs[32][72];
    __shared__ uint32_t Bw[32][136];
    __shared__ float wts[32];
    int bx = blockIdx.x;
    int h = bx % 3; int rest = bx / 3;
    int c = rest & 15; int bb = rest >> 4;
    int m0 = bb * LSEQ + c * CHUNK;
    int tid = threadIdx.x, lane = tid & 31, wid = tid >> 5;   // 256 thr / 8 warps
    int wm = (wid & 3) * 16;
    int wn = (wid >> 2) * 64;
    float dAl = g_dAc[(m0 + 255) * NH + h];
    float acc[8][4] = {};
    for (int tc = 0; tc < CHUNK; tc += 32) {
        __syncthreads();
        if (tid < 32) {
            int t = tc + tid;
            wts[tid] = __expf(dAl - g_dAc[(m0 + t) * NH + h]) * g_dt[(m0 + t) * NH + h];
        }
        __syncthreads();
        for (int i = tid; i < 32 * 16; i += 256) {
            int r = i >> 4, c4 = (i & 15) * 4;
            uint2 raw = *(const uint2*)&g_xBC[(m0 + tc + r) * CONVD + h * HD + c4];
            Xs[r][c4 + 0] = BF_LO(raw.x); Xs[r][c4 + 1] = BF_HI(raw.x);
            Xs[r][c4 + 2] = BF_LO(raw.y); Xs[r][c4 + 3] = BF_HI(raw.y);
        }
        for (int i = tid; i < 32 * 16; i += 256) {
            int r = i >> 4, c8 = (i & 15) * 8;
            float w = wts[r];
            uint4 raw = *(const uint4*)&g_xBC[(m0 + tc + r) * CONVD + DIN + c8];
            Bw[r][c8 + 0] = f2tf(w * blo(raw.x));
            Bw[r][c8 + 1] = f2tf(w * bhi(raw.x));
            Bw[r][c8 + 2] = f2tf(w * blo(raw.y));
            Bw[r][c8 + 3] = f2tf(w * bhi(raw.y));
            Bw[r][c8 + 4] = f2tf(w * blo(raw.z));
            Bw[r][c8 + 5] = f2tf(w * bhi(raw.z));
            Bw[r][c8 + 6] = f2tf(w * blo(raw.w));
            Bw[r][c8 + 7] = f2tf(w * bhi(raw.w));
        }
        __syncthreads();
        #pragma unroll
        for (int k8 = 0; k8 < 32; k8 += 8) {
            int rA = wm + (lane >> 2), kA = k8 + (lane & 3);
            uint32_t a0 = Xs[kA][rA],     a1 = Xs[kA][rA + 8];
            uint32_t a2 = Xs[kA + 4][rA], a3 = Xs[kA + 4][rA + 8];
            #pragma unroll
            for (int ni = 0; ni < 8; ni++) {
                int cn = wn + ni * 8 + (lane >> 2);
                mma_tf32(acc[ni], a0, a1, a2, a3, Bw[kA][cn], Bw[kA + 4][cn]);
            }
        }
    }
    int blk = (bb * 16 + c) * 3 + h;
    int gid = lane >> 2, tig = lane & 3;
    #pragma unroll
    for (int ni = 0; ni < 8; ni++) {
        int p0 = wm + gid;
        int n0 = wn + ni * 8 + tig * 2;
        float* dst = &g_states[blk * (HD * DSTATE)];
        dst[p0 * DSTATE + n0]           = acc[ni][0];
        dst[p0 * DSTATE + n0 + 1]       = acc[ni][1];
        dst[(p0 + 8) * DSTATE + n0]     = acc[ni][2];
        dst[(p0 + 8) * DSTATE + n0 + 1] = acc[ni][3];
    }
}

// ============ kernel 7: inter-chunk recurrence ============
__global__ void k_recur() {
    int bxs = blockIdx.x;          // 192
    int slice = bxs & 7;
    int bh = bxs >> 3;
    int bb = bh / 3, h = bh % 3;
    int tid = threadIdx.x;         // 256
    float hr[4] = {0.f, 0.f, 0.f, 0.f};
    for (int c = 0; c < NC; c++) {
        int blk = (bb * 16 + c) * 3 + h;
        float decay = __expf(g_dAc[(bb * LSEQ + c * CHUNK + 255) * NH + h]);
        #pragma unroll
        for (int r = 0; r < 4; r++) {
            int idx = blk * (HD * DSTATE) + slice * 1024 + r * 256 + tid;
            g_prev[idx] = hr[r];
            hr[r] = fmaf(decay, hr[r], g_states[idx]);
        }
    }
}

// ============ kernel 8: inter-chunk y correction via bf16 MMA ============
__global__ void k_ycorr() {
    extern __shared__ uint32_t ysm[];
    uint32_t (*prevS)[68] = (uint32_t(*)[68])ysm;
    uint32_t (*Cs)[68]    = (uint32_t(*)[68])(ysm + 64 * 68);
    float* exps           = (float*)(ysm + 2 * 64 * 68);
    int bx = blockIdx.x;
    int h = bx % 3; int rest = bx / 3;
    int c = rest & 15; int bb = rest >> 4;
    int m0 = bb * LSEQ + c * CHUNK;
    int blk = (bb * 16 + c) * 3 + h;
    int tid = threadIdx.x, lane = tid & 31, wid = tid >> 5;   // 128 thr / 4 warps
    for (int i = tid; i < 64 * 32; i += 128) {
        int p = i >> 5, c4 = (i & 31) * 4;
        float4 v = *(const float4*)&g_prev[blk * (HD * DSTATE) + p * DSTATE + c4];
        prevS[p][(c4 >> 1)]     = packbf(v.x, v.y);
        prevS[p][(c4 >> 1) + 1] = packbf(v.z, v.w);
    }
    int gid = lane >> 2, tig = lane & 3;
    for (int stile = 0; stile < 4; stile++) {
        __syncthreads();
        for (int i = tid; i < 64 * 16; i += 128) {
            int r = i >> 4, q = i & 15;
            uint4 raw = *(const uint4*)&g_xBC[(m0 + stile * 64 + r) * CONVD + (DIN + DSTATE) + q * 8];
            *(uint4*)&Cs[r][q * 4] = raw;
        }
        if (tid < 64) exps[tid] = __expf(g_dAc[(m0 + stile * 64 + tid) * NH + h]);
        __syncthreads();
        float acc[8][4] = {};
        #pragma unroll
        for (int k16 = 0; k16 < 8; k16++) {
            int rA = wid * 16 + gid;
            int kp = k16 * 8 + (lane & 3);
            uint32_t a0 = Cs[rA][kp],     a1 = Cs[rA + 8][kp];
            uint32_t a2 = Cs[rA][kp + 4], a3 = Cs[rA + 8][kp + 4];
            #pragma unroll
            for (int ni = 0; ni < 8; ni++) {
                int cn = ni * 8 + gid;
                mma_bf16(acc[ni], a0, a1, a2, a3, prevS[cn][kp], prevS[cn][kp + 4]);
            }
        }
        #pragma unroll
        for (int ni = 0; ni < 8; ni++) {
            int p = ni * 8 + tig * 2;
            int s0 = wid * 16 + gid;
            int m1 = m0 + stile * 64 + s0;
            int m2 = m1 + 8;
            float eA1 = exps[s0], eA2 = exps[s0 + 8];
            uint32_t y1 = *(uint32_t*)&g_y[m1 * DIN + h * HD + p];
            uint32_t y2 = *(uint32_t*)&g_y[m2 * DIN + h * HD + p];
            float v10 = blo(y1) + eA1 * acc[ni][0];
            float v11 = bhi(y1) + eA1 * acc[ni][1];
            float v20 = blo(y2) + eA2 * acc[ni][2];
            float v21 = bhi(y2) + eA2 * acc[ni][3];
            *(uint32_t*)&g_y[m1 * DIN + h * HD + p] = packbf(v10, v11);
            *(uint32_t*)&g_y[m2 * DIN + h * HD + p] = packbf(v20, v21);
        }
    }
}
#define SMEM_YCORR ((2 * 64 * 68) * 4 + 64 * 4)

// ============ kernel 9: fused gate+rmsnorm+out_proj via bf16 MMA ============
__global__ void k_gateproj(const float* __restrict__ gw, const float* __restrict__ W) {
    extern __shared__ uint32_t gpm[];
    uint32_t (*As)[100] = (uint32_t(*)[100])gpm;
    uint32_t (*Bs)[100] = (uint32_t(*)[100])(gpm + 128 * 100);
    int bm = blockIdx.x * 128;
    int tid = threadIdx.x, lane = tid & 31, wid = tid >> 5;
    for (int i = tid; i < 96 * 48; i += 256) {
        int r = i / 48, q = i - r * 48;
        float4 v = *(const float4*)&W[r * DIN + q * 4];
        Bs[r][q * 2]     = packbf(v.x, v.y);
        Bs[r][q * 2 + 1] = packbf(v.z, v.w);
    }
    int rgrp = lane >> 3, cch = lane & 7;
    int cbase = cch * 4;
    for (int pass = 0; pass < 4; pass++) {
        int row = pass * 32 + wid * 4 + rgrp;
        int m = bm + row;
        float vbuf[24];
        float ss = 0.f;
        #pragma unroll
        for (int j = 0; j < 6; j++) {
            int col = cbase + j * 32;
            uint2 yu = *(const uint2*)&g_y[m * DIN + col];
            uint2 zu = *(const uint2*)&g_zxbcdt[(size_t)m * NPROJ_S + col];
            float y0 = blo(yu.x), y1 = bhi(yu.x);
            float y2 = blo(yu.y), y3 = bhi(yu.y);
            float z0 = blo(zu.x), z1 = bhi(zu.x);
            float z2 = blo(zu.y), z3 = bhi(zu.y);
            float v0 = y0 * (z0 / (1.0f + __expf(-z0)));
            float v1 = y1 * (z1 / (1.0f + __expf(-z1)));
            float v2 = y2 * (z2 / (1.0f + __expf(-z2)));
            float v3 = y3 * (z3 / (1.0f + __expf(-z3)));
            vbuf[j*4+0] = v0; vbuf[j*4+1] = v1; vbuf[j*4+2] = v2; vbuf[j*4+3] = v3;
            ss = fmaf(v0, v0, fmaf(v1, v1, fmaf(v2, v2, fmaf(v3, v3, ss))));
        }
        ss += __shfl_xor_sync(0xffffffffu, ss, 1);
        ss += __shfl_xor_sync(0xffffffffu, ss, 2);
        ss += __shfl_xor_sync(0xffffffffu, ss, 4);
        float rr = rsqrtf(ss / 192.0f + 1e-5f);
        #pragma unroll
        for (int j = 0; j < 6; j++) {
            int col = cbase + j * 32;
            float g0 = gw[col], g1 = gw[col + 1], g2 = gw[col + 2], g3 = gw[col + 3];
            As[row][(col >> 1)]     = packbf(vbuf[j*4+0] * rr * g0, vbuf[j*4+1] * rr * g1);
            As[row][(col >> 1) + 1] = packbf(vbuf[j*4+2] * rr * g2, vbuf[j*4+3] * rr * g3);
        }
    }
    __syncthreads();
    int wm = (wid & 3) * 32;
    int wn = (wid >> 2) * 48;
    float acc[2][6][4] = {};
    #pragma unroll
    for (int k16 = 0; k16 < 12; k16++) {
        int kp = k16 * 8 + (lane & 3);
        uint32_t af[2][4];
        #pragma unroll
        for (int mi = 0; mi < 2; mi++) {
            int r = wm + mi * 16 + (lane >> 2);
            af[mi][0] = As[r][kp];     af[mi][1] = As[r + 8][kp];
            af[mi][2] = As[r][kp + 4]; af[mi][3] = As[r + 8][kp + 4];
        }
        #pragma unroll
        for (int ni = 0; ni < 6; ni++) {
            int cn = wn + ni * 8 + (lane >> 2);
            uint32_t b0 = Bs[cn][kp], b1 = Bs[cn][kp + 4];
            #pragma unroll
            for (int mi = 0; mi < 2; mi++)
                mma_bf16(acc[mi][ni], af[mi][0], af[mi][1], af[mi][2], af[mi][3], b0, b1);
        }
    }
    int gid = lane >> 2, tig = lane & 3;
    #pragma unroll
    for (int mi = 0; mi < 2; mi++) {
        int r0 = bm + wm + mi * 16 + gid;
        #pragma unroll
        for (int ni = 0; ni < 6; ni++) {
            int c0 = wn + ni * 8 + tig * 2;
            *(__nv_bfloat162*)&g_ysd[r0 * CMODEL + c0] =
                __floats2bfloat162_rn(acc[mi][ni][0], acc[mi][ni][1]);
            *(__nv_bfloat162*)&g_ysd[(r0 + 8) * CMODEL + c0] =
                __floats2bfloat162_rn(acc[mi][ni][2], acc[mi][ni][3]);
        }
    }
}
#define SMEM_GATEPROJ ((128 * 100 + 96 * 100) * 4)

// ============ kernel 10: un-scan + residual (16-pixel tiles) ============
__global__ void k_unscan(const float* __restrict__ x, float* __restrict__ out) {
    __shared__ float sy[96][17];
    int bi = blockIdx.x >> 8;
    int l0 = (blockIdx.x & 255) * 16;
    int tid = threadIdx.x;                 // 256
    for (int i = tid; i < 1536; i += 256) {
        int ll = i / 96, ch = i - ll * 96;
        int l = l0 + ll;
        int hh = l >> 6, ww = l & 63;
        int lt = (ww << 6) + hh;
        float v = __bfloat162float(g_ysd[(((bi * 4 + 0) << 12) + l) * 96 + ch])
                + __bfloat162float(g_ysd[(((bi * 4 + 1) << 12) + (4095 - l)) * 96 + ch])
                + __bfloat162float(g_ysd[(((bi * 4 + 2) << 12) + lt) * 96 + ch])
                + __bfloat162float(g_ysd[(((bi * 4 + 3) << 12) + (4095 - lt)) * 96 + ch]);
        sy[ch][ll] = 0.25f * v;
    }
    __syncthreads();
    for (int i = tid; i < 96 * 16; i += 256) {
        int ch = i >> 4, ll = i & 15;
        int idx = ((bi * 96 + ch) << 12) + l0 + ll;
        out[idx] = x[idx] + sy[ch][ll];
    }
}

// ---------------- launch (fork/join stream overlap) ----------------
extern "C" void kernel_launch(void* const* d_in, const int* in_sizes, int n_in,
                              void* d_out, int out_size) {
    const float* x          = (const float*)d_in[0];
    const float* norm_w     = (const float*)d_in[1];
    const float* in_proj_w  = (const float*)d_in[2];
    const float* conv_w     = (const float*)d_in[3];
    const float* conv_b     = (const float*)d_in[4];
    const float* dt_bias    = (const float*)d_in[5];
    const float* A_log      = (const float*)d_in[6];
    const float* Dp         = (const float*)d_in[7];
    const float* gnorm_w    = (const float*)d_in[8];
    const float* out_proj_w = (const float*)d_in[9];
    float* out = (float*)d_out;

    static cudaStream_t sB = 0;
    static cudaEvent_t e1 = 0, e2 = 0, e3 = 0, e4 = 0;
    static int inited = 0;
    if (!inited) {
        cudaFuncSetAttribute(k_inproj_mma, cudaFuncAttributeMaxDynamicSharedMemorySize, SMEM_INPROJ);
        cudaFuncSetAttribute(k_intra_mma, cudaFuncAttributeMaxDynamicSharedMemorySize, SMEM_INTRA);
        cudaFuncSetAttribute(k_ycorr, cudaFuncAttributeMaxDynamicSharedMemorySize, SMEM_YCORR);
        cudaFuncSetAttribute(k_gateproj, cudaFuncAttributeMaxDynamicSharedMemorySize, SMEM_GATEPROJ);
        cudaStreamCreateWithFlags(&sB, cudaStreamNonBlocking);
        cudaEventCreateWithFlags(&e1, cudaEventDisableTiming);
        cudaEventCreateWithFlags(&e2, cudaEventDisableTiming);
        cudaEventCreateWithFlags(&e3, cudaEventDisableTiming);
        cudaEventCreateWithFlags(&e4, cudaEventDisableTiming);
        inited = 1;
    }

    k_rms_scan<<<BATCH * 256, 256>>>(x, norm_w);
    k_inproj_mma<<<dim3(6, MROWS / 128), 256, SMEM_INPROJ>>>(in_proj_w);
    cudaEventRecord(e1, 0);

    cudaStreamWaitEvent(sB, e1, 0);
    k_dt<<<BB * NC, CHUNK, 0, sB>>>(dt_bias, A_log);
    cudaEventRecord(e3, sB);

    k_conv<<<MROWS / 32, 224>>>(conv_w, conv_b);
    cudaEventRecord(e2, 0);

    cudaStreamWaitEvent(sB, e2, 0);
    k_states<<<BB * NC * NH, 256, 0, sB>>>();
    k_recur<<<BB * NH * 8, 256, 0, sB>>>();
    cudaEventRecord(e4, sB);

    cudaStreamWaitEvent(0, e3, 0);
    k_intra_mma<<<BB * NC * NH * 4, 128, SMEM_INTRA>>>(Dp);

    cudaStreamWaitEvent(0, e4, 0);
    k_ycorr<<<BB * NC * NH, 128, SMEM_YCORR>>>();
    k_gateproj<<<MROWS / 128, 256, SMEM_GATEPROJ>>>(gnorm_w, out_proj_w);
    k_unscan<<<BATCH * 256, 256>>>(x, out);
}

// round 17
// speedup vs baseline: 1.0270x; 1.0270x over previous
#include <cuda_runtime.h>
#include <cuda_bf16.h>
#include <math.h>
#include <stdint.h>

// ---------------- problem constants ----------------
#define BATCH   2
#define CMODEL  96
#define LSEQ    4096
#define BB      8
#define DIN     192
#define DSTATE  128
#define CONVD   448
#define NH      3
#define HD      64
#define NPROJ   643
#define NPROJ_S 644
#define CHUNK   256
#define NC      16
#define MROWS   (BB*LSEQ)       // 32768

// ---------------- scratch (16B-aligned bf16 buffers) ----------------
__device__ __align__(16) __nv_bfloat16 g_xs[MROWS * CMODEL];
__device__ __align__(16) __nv_bfloat16 g_zxbcdt[MROWS * NPROJ_S];
__device__ float g_dtraw[MROWS * NH];
__device__ __align__(16) __nv_bfloat16 g_xBC[MROWS * CONVD];
__device__ float g_dt[MROWS * NH];
__device__ float g_dAc[MROWS * NH];
__device__ __align__(16) __nv_bfloat16 g_y[MROWS * DIN];
__device__ __align__(16) __nv_bfloat16 g_ysd[MROWS * CMODEL];
__device__ float g_states[BB * NC * NH * HD * DSTATE];
__device__ float g_prev[BB * NC * NH * HD * DSTATE];

// ---------------- mma helpers ----------------
__device__ __forceinline__ uint32_t f2tf(float f) {
    uint32_t u;
    asm("cvt.rna.tf32.f32 %0, %1;" : "=r"(u) : "f"(f));
    return u;
}
__device__ __forceinline__ void mma_tf32(float c[4], uint32_t a0, uint32_t a1, uint32_t a2, uint32_t a3,
                                         uint32_t b0, uint32_t b1) {
    asm volatile("mma.sync.aligned.m16n8k8.row.col.f32.tf32.tf32.f32 "
                 "{%0,%1,%2,%3}, {%4,%5,%6,%7}, {%8,%9}, {%0,%1,%2,%3};"
                 : "+f"(c[0]), "+f"(c[1]), "+f"(c[2]), "+f"(c[3])
                 : "r"(a0), "r"(a1), "r"(a2), "r"(a3), "r"(b0), "r"(b1));
}
__device__ __forceinline__ void mma_bf16(float c[4], uint32_t a0, uint32_t a1, uint32_t a2, uint32_t a3,
                                         uint32_t b0, uint32_t b1) {
    asm volatile("mma.sync.aligned.m16n8k16.row.col.f32.bf16.bf16.f32 "
                 "{%0,%1,%2,%3}, {%4,%5,%6,%7}, {%8,%9}, {%0,%1,%2,%3};"
                 : "+f"(c[0]), "+f"(c[1]), "+f"(c[2]), "+f"(c[3])
                 : "r"(a0), "r"(a1), "r"(a2), "r"(a3), "r"(b0), "r"(b1));
}
#define BF_LO(u) ((u) << 16)
#define BF_HI(u) ((u) & 0xFFFF0000u)
__device__ __forceinline__ uint32_t packbf(float a, float b) {
    union { __nv_bfloat162 h2; uint32_t u; } p;
    p.h2 = __floats2bfloat162_rn(a, b);
    return p.u;
}
__device__ __forceinline__ float blo(uint32_t u) { return __uint_as_float(BF_LO(u)); }
__device__ __forceinline__ float bhi(uint32_t u) { return __uint_as_float(BF_HI(u)); }

// ============ kernel 1: rmsnorm + cross-scan -> bf16 (16-pixel tiles) ============
__global__ void k_rms_scan(const float* __restrict__ x, const float* __restrict__ norm_w) {
    __shared__ float sx[96][17];
    __shared__ float rs[16];
    __shared__ float wsh[96];
    int bi = blockIdx.x >> 8;
    int l0 = (blockIdx.x & 255) * 16;
    int tid = threadIdx.x;                 // 256
    if (tid < 96) wsh[tid] = norm_w[tid];
    for (int i = tid; i < 96 * 16; i += 256) {
        int ch = i >> 4, ll = i & 15;
        sx[ch][ll] = x[((bi * 96 + ch) << 12) + l0 + ll];
    }
    __syncthreads();
    if (tid < 16) {
        float ssum = 0.f;
        #pragma unroll 8
        for (int ch = 0; ch < 96; ch++) { float v = sx[ch][tid]; ssum = fmaf(v, v, ssum); }
        rs[tid] = rsqrtf(ssum / 96.0f + 1.1920929e-07f);
    }
    __syncthreads();
    for (int i = tid; i < 768; i += 256) {
        int ll = i / 48, cp = i - ll * 48;
        int ch = cp * 2;
        int l = l0 + ll;
        float r = rs[ll];
        float nv0 = sx[ch][ll] * r * wsh[ch];
        float nv1 = sx[ch + 1][ll] * r * wsh[ch + 1];
        __nv_bfloat162 pk = __floats2bfloat162_rn(nv0, nv1);
        int hh = l >> 6, ww = l & 63;
        int lt = (ww << 6) + hh;
        *(__nv_bfloat162*)&g_xs[((((bi * 4 + 0) << 12) + l) * 96) + ch] = pk;
        *(__nv_bfloat162*)&g_xs[((((bi * 4 + 1) << 12) + (4095 - l)) * 96) + ch] = pk;
        *(__nv_bfloat162*)&g_xs[((((bi * 4 + 2) << 12) + lt) * 96) + ch] = pk;
        *(__nv_bfloat162*)&g_xs[((((bi * 4 + 3) << 12) + (4095 - lt)) * 96) + ch] = pk;
    }
}

// ============ kernel 2: in_proj GEMM via bf16 MMA (M=32768, N=643, K=96) ============
__global__ void k_inproj_mma(const float* __restrict__ W) {
    extern __shared__ uint32_t ipm[];
    uint32_t (*As)[52] = (uint32_t(*)[52])ipm;
    uint32_t (*Bs)[52] = (uint32_t(*)[52])(ipm + 128 * 52);
    int bm = blockIdx.y * 128;
    int bn = blockIdx.x * 128;
    int tid = threadIdx.x;
    int lane = tid & 31, wid = tid >> 5;
    int wm = (wid & 1) * 64;
    int wn = (wid >> 1) * 32;
    for (int i = tid; i < 128 * 12; i += 256) {
        int r = i / 12, q = i - r * 12;
        uint4 raw = *(const uint4*)&g_xs[(bm + r) * CMODEL + q * 8];
        *(uint4*)&As[r][q * 4] = raw;
    }
    for (int i = tid; i < 128 * 24; i += 256) {
        int r = i / 24, q = i - r * 24;
        int n = bn + r;
        float4 v = make_float4(0.f, 0.f, 0.f, 0.f);
        if (n < NPROJ) v = *(const float4*)&W[n * CMODEL + q * 4];
        Bs[r][q * 2]     = packbf(v.x, v.y);
        Bs[r][q * 2 + 1] = packbf(v.z, v.w);
    }
    __syncthreads();
    float acc[4][4][4] = {};
    #pragma unroll
    for (int k16 = 0; k16 < 6; k16++) {
        int kp = k16 * 8 + (lane & 3);
        uint32_t af[4][4], bf[4][2];
        int rA = lane >> 2;
        #pragma unroll
        for (int mi = 0; mi < 4; mi++) {
            int r = wm + mi * 16 + rA;
            af[mi][0] = As[r][kp];     af[mi][1] = As[r + 8][kp];
            af[mi][2] = As[r][kp + 4]; af[mi][3] = As[r + 8][kp + 4];
        }
        #pragma unroll
        for (int ni = 0; ni < 4; ni++) {
            int cn = wn + ni * 8 + rA;
            bf[ni][0] = Bs[cn][kp];
            bf[ni][1] = Bs[cn][kp + 4];
        }
        #pragma unroll
        for (int mi = 0; mi < 4; mi++)
            #pragma unroll
            for (int ni = 0; ni < 4; ni++)
                mma_bf16(acc[mi][ni], af[mi][0], af[mi][1], af[mi][2], af[mi][3],
                         bf[ni][0], bf[ni][1]);
    }
    int gid = lane >> 2, tig = lane & 3;
    #pragma unroll
    for (int mi = 0; mi < 4; mi++) {
        int r0 = bm + wm + mi * 16 + gid;
        #pragma unroll
        for (int ni = 0; ni < 4; ni++) {
            int c0 = bn + wn + ni * 8 + tig * 2;
            float a0 = acc[mi][ni][0], a1 = acc[mi][ni][1];
            float a2 = acc[mi][ni][2], a3 = acc[mi][ni][3];
            if (c0 + 1 < NPROJ) {
                *(__nv_bfloat162*)&g_zxbcdt[r0 * NPROJ_S + c0]       = __floats2bfloat162_rn(a0, a1);
                *(__nv_bfloat162*)&g_zxbcdt[(r0 + 8) * NPROJ_S + c0] = __floats2bfloat162_rn(a2, a3);
            } else if (c0 < NPROJ) {
                g_zxbcdt[r0 * NPROJ_S + c0]       = __float2bfloat16(a0);
                g_zxbcdt[(r0 + 8) * NPROJ_S + c0] = __float2bfloat16(a2);
            }
            int hh0 = c0 - (DIN + CONVD);
            if (hh0 >= 0 && hh0 < NH) {
                g_dtraw[r0 * NH + hh0] = a0;
                g_dtraw[(r0 + 8) * NH + hh0] = a2;
            }
            if (hh0 + 1 >= 0 && hh0 + 1 < NH) {
                g_dtraw[r0 * NH + hh0 + 1] = a1;
                g_dtraw[(r0 + 8) * NH + hh0 + 1] = a3;
            }
        }
    }
}
#define SMEM_INPROJ (2 * 128 * 52 * 4)

// ============ kernel 3: dt softplus + per-chunk cumsum ============
__global__ void k_dt(const float* __restrict__ dt_bias, const float* __restrict__ A_log) {
    int cb = blockIdx.x;
    int t  = threadIdx.x;                 // 256
    int m  = cb * CHUNK + t;
    int lane = t & 31, wid = t >> 5;
    __shared__ float wsum[8], woff[8];
    for (int h = 0; h < NH; h++) {
        float raw = g_dtraw[m * NH + h] + dt_bias[h];
        float dtv = (raw > 20.0f) ? raw : log1pf(expf(raw));
        g_dt[m * NH + h] = dtv;
        float Ah = -expf(A_log[h]);
        float s = dtv * Ah;
        #pragma unroll
        for (int o = 1; o < 32; o <<= 1) {
            float n = __shfl_up_sync(0xffffffffu, s, o);
            if (lane >= o) s += n;
        }
        if (lane == 31) wsum[wid] = s;
        __syncthreads();
        if (t < 8) {
            float ws = wsum[t];
            #pragma unroll
            for (int o = 1; o < 8; o <<= 1) {
                float n = __shfl_up_sync(0xffu, ws, o);
                if (t >= o) ws += n;
            }
            woff[t] = ws;
        }
        __syncthreads();
        float off = wid ? woff[wid - 1] : 0.0f;
        g_dAc[m * NH + h] = s + off;
        __syncthreads();
    }
}

// ============ kernel 4: depthwise causal conv + SiLU, sliding window (R15) ============
__global__ void k_conv(const float* __restrict__ cw, const float* __restrict__ cb) {
    int tid = threadIdx.x;                 // 224
    int q = tid % 112, rg = tid / 112;
    int c4 = q * 4;
    int base = blockIdx.x * 8 + rg * 4;
    float4 r0 = *(const float4*)&cw[(c4 + 0) * 4];
    float4 r1 = *(const float4*)&cw[(c4 + 1) * 4];
    float4 r2 = *(const float4*)&cw[(c4 + 2) * 4];
    float4 r3 = *(const float4*)&cw[(c4 + 3) * 4];
    float4 bias = *(const float4*)&cb[c4];
    const __nv_bfloat16* src = g_zxbcdt + DIN + c4;
    bool seqstart = ((base & 4095) == 0);
    float4 vm3, vm2, vm1;
    if (seqstart) {
        vm3 = make_float4(0.f, 0.f, 0.f, 0.f);
        vm2 = vm3; vm1 = vm3;
    } else {
        uint2 u3 = *(const uint2*)&src[(base - 3) * NPROJ_S];
        uint2 u2 = *(const uint2*)&src[(base - 2) * NPROJ_S];
        uint2 u1 = *(const uint2*)&src[(base - 1) * NPROJ_S];
        vm3 = make_float4(blo(u3.x), bhi(u3.x), blo(u3.y), bhi(u3.y));
        vm2 = make_float4(blo(u2.x), bhi(u2.x), blo(u2.y), bhi(u2.y));
        vm1 = make_float4(blo(u1.x), bhi(u1.x), blo(u1.y), bhi(u1.y));
    }
    #pragma unroll
    for (int i = 0; i < 4; i++) {
        uint2 uc = *(const uint2*)&src[(base + i) * NPROJ_S];
        float4 vc = make_float4(blo(uc.x), bhi(uc.x), blo(uc.y), bhi(uc.y));
        float4 a;
        a.x = bias.x + r0.x * vm3.x + r0.y * vm2.x + r0.z * vm1.x + r0.w * vc.x;
        a.y = bias.y + r1.x * vm3.y + r1.y * vm2.y + r1.z * vm1.y + r1.w * vc.y;
        a.z = bias.z + r2.x * vm3.z + r2.y * vm2.z + r2.z * vm1.z + r2.w * vc.z;
        a.w = bias.w + r3.x * vm3.w + r3.y * vm2.w + r3.z * vm1.w + r3.w * vc.w;
        float ox = a.x / (1.0f + __expf(-a.x));
        float oy = a.y / (1.0f + __expf(-a.y));
        float oz = a.z / (1.0f + __expf(-a.z));
        float ow = a.w / (1.0f + __expf(-a.w));
        uint2 pk;
        pk.x = packbf(ox, oy);
        pk.y = packbf(oz, ow);
        *(uint2*)&g_xBC[(base + i) * CONVD + c4] = pk;
        vm3 = vm2; vm2 = vm1; vm1 = vc;
    }
}

// ============ kernel 5: intra-chunk SSD; GEMM1 & GEMM2 bf16 MMA ============
__global__ void k_intra_mma(const float* __restrict__ Dp) {
    extern __shared__ uint32_t smb[];
    uint32_t (*Cs)[68]  = (uint32_t(*)[68])smb;
    uint32_t (*Bs)[68]  = (uint32_t(*)[68])(smb + 64 * 68);
    uint32_t (*XsT)[33] = (uint32_t(*)[33])(smb + 2 * 64 * 68);
    uint32_t (*Ssm)[33] = (uint32_t(*)[33])Bs;
    float* dAs = (float*)(smb + 2 * 64 * 68 + 64 * 33);
    float* dAt = dAs + 64;
    float* dtt = dAt + 64;

    int bx = blockIdx.x;
    int st = 3 - (bx & 3);
    int rest = bx >> 2;
    int h = rest % 3; rest /= 3;
    int c = rest & 15;
    int bb = rest >> 4;
    int m0 = bb * LSEQ + c * CHUNK;
    int tid = threadIdx.x, lane = tid & 31, wid = tid >> 5;

    int sbase = m0 + st * 64;
    for (int i = tid; i < 64 * 16; i += 128) {
        int r = i >> 4, q = i & 15;
        uint4 raw = *(const uint4*)&g_xBC[(sbase + r) * CONVD + (DIN + DSTATE) + q * 8];
        *(uint4*)&Cs[r][q * 4] = raw;
    }
    if (tid < 64) dAs[tid] = g_dAc[(sbase + tid) * NH + h];

    float accY[8][4] = {};

    for (int tt = 0; tt <= st; tt++) {
        int tbase = m0 + tt * 64;
        __syncthreads();
        for (int i = tid; i < 64 * 16; i += 128) {
            int r = i >> 4, q = i & 15;
            uint4 raw = *(const uint4*)&g_xBC[(tbase + r) * CONVD + DIN + q * 8];
            *(uint4*)&Bs[r][q * 4] = raw;
        }
        for (int i = tid; i < 32 * 16; i += 128) {
            int tp = i >> 4, p4 = (i & 15) * 4;
            uint2 e = *(const uint2*)&g_xBC[(tbase + 2 * tp)     * CONVD + h * HD + p4];
            uint2 o = *(const uint2*)&g_xBC[(tbase + 2 * tp + 1) * CONVD + h * HD + p4];
            XsT[p4 + 0][tp] = (e.x & 0xFFFFu)  | (o.x << 16);
            XsT[p4 + 1][tp] = (e.x >> 16)      | (o.x & 0xFFFF0000u);
            XsT[p4 + 2][tp] = (e.y & 0xFFFFu)  | (o.y << 16);
            XsT[p4 + 3][tp] = (e.y >> 16)      | (o.y & 0xFFFF0000u);
        }
        if (tid < 64) {
            dAt[tid] = g_dAc[(tbase + tid) * NH + h];
            dtt[tid] = g_dt[(tbase + tid) * NH + h];
        }
        __syncthreads();

        float S[8][4] = {};
        #pragma unroll
        for (int k16 = 0; k16 < 8; k16++) {
            int rA = wid * 16 + (lane >> 2);
            int kp = k16 * 8 + (lane & 3);
            uint32_t a0 = Cs[rA][kp],     a1 = Cs[rA + 8][kp];
            uint32_t a2 = Cs[rA][kp + 4], a3 = Cs[rA + 8][kp + 4];
            #pragma unroll
            for (int nf = 0; nf < 8; nf++) {
                int t = nf * 8 + (lane >> 2);
                mma_bf16(S[nf], a0, a1, a2, a3, Bs[t][kp], Bs[t][kp + 4]);
            }
        }
        __syncthreads();
        {
            int gid = lane >> 2, tig = lane & 3;
            #pragma unroll
            for (int nf = 0; nf < 8; nf++) {
                int tl = nf * 8 + tig * 2;
                int sl = wid * 16 + gid;
                bool ok0 = (tt < st) || (tl     <= sl);
                bool ok1 = (tt < st) || (tl + 1 <= sl);
                bool ok2 = (tt < st) || (tl     <= sl + 8);
                bool ok3 = (tt < st) || (tl + 1 <= sl + 8);
                float f0 = ok0 ? __expf(dAs[sl]     - dAt[tl])     * dtt[tl]     : 0.0f;
                float f1 = ok1 ? __expf(dAs[sl]     - dAt[tl + 1]) * dtt[tl + 1] : 0.0f;
                float f2 = ok2 ? __expf(dAs[sl + 8] - dAt[tl])     * dtt[tl]     : 0.0f;
                float f3 = ok3 ? __expf(dAs[sl + 8] - dAt[tl + 1]) * dtt[tl + 1] : 0.0f;
                Ssm[sl][nf * 4 + tig]     = packbf(S[nf][0] * f0, S[nf][1] * f1);
                Ssm[sl + 8][nf * 4 + tig] = packbf(S[nf][2] * f2, S[nf][3] * f3);
            }
        }
        __syncthreads();
        #pragma unroll
        for (int k16 = 0; k16 < 4; k16++) {
            int rA = wid * 16 + (lane >> 2);
            int kp = k16 * 8 + (lane & 3);
            uint32_t a0 = Ssm[rA][kp],     a1 = Ssm[rA + 8][kp];
            uint32_t a2 = Ssm[rA][kp + 4], a3 = Ssm[rA + 8][kp + 4];
            #pragma unroll
            for (int nf = 0; nf < 8; nf++) {
                int pn = nf * 8 + (lane >> 2);
                mma_bf16(accY[nf], a0, a1, a2, a3, XsT[pn][kp], XsT[pn][kp + 4]);
            }
        }
    }
    float Dh = Dp[h];
    int gid = lane >> 2, tig = lane & 3;
    #pragma unroll
    for (int nf = 0; nf < 8; nf++) {
        int sl = wid * 16 + gid;
        int s = st * 64 + sl;
        int p = nf * 8 + tig * 2;
        bool odd = (sl & 1);
        uint32_t ua = XsT[p][sl >> 1],       ub = XsT[p + 1][sl >> 1];
        uint32_t uc = XsT[p][(sl + 8) >> 1], ud = XsT[p + 1][(sl + 8) >> 1];
        float x00 = __uint_as_float(odd ? BF_HI(ua) : BF_LO(ua));
        float x01 = __uint_as_float(odd ? BF_HI(ub) : BF_LO(ub));
        float x10 = __uint_as_float(odd ? BF_HI(uc) : BF_LO(uc));
        float x11 = __uint_as_float(odd ? BF_HI(ud) : BF_LO(ud));
        *(__nv_bfloat162*)&g_y[(m0 + s) * DIN + h * HD + p] =
            __floats2bfloat162_rn(accY[nf][0] + Dh * x00, accY[nf][1] + Dh * x01);
        *(__nv_bfloat162*)&g_y[(m0 + s + 8) * DIN + h * HD + p] =
            __floats2bfloat162_rn(accY[nf][2] + Dh * x10, accY[nf][3] + Dh * x11);
    }
}
#define SMEM_INTRA ((2 * 64 * 68 + 64 * 33 + 3 * 64) * 4)

// ============ kernel 6: per-chunk end states via tf32 MMA ============
__global__ void k_states() {
    __shared__ uint32_t Xs[32][72];
    __shared__ uint32_t Bw[32][136];
    __shared__ float wts[32];
    int bx = blockIdx.x;
    int h = bx % 3; int rest = bx / 3;
    int c = rest & 15; int bb = rest >> 4;
    int m0 = bb * LSEQ + c * CHUNK;
    int tid = threadIdx.x, lane = tid & 31, wid = tid >> 5;   // 256 thr / 8 warps
    int wm = (wid & 3) * 16;
    int wn = (wid >> 2) * 64;
    float dAl = g_dAc[(m0 + 255) * NH + h];
    float acc[8][4] = {};
    for (int tc = 0; tc < CHUNK; tc += 32) {
        __syncthreads();
        if (tid < 32) {
            int t = tc + tid;
            wts[tid] = __expf(dAl - g_dAc[(m0 + t) * NH + h]) * g_dt[(m0 + t) * NH + h];
        }
        __syncthreads();
        for (int i = tid; i < 32 * 16; i += 256) {
            int r = i >> 4, c4 = (i & 15) * 4;
            uint2 raw = *(const uint2*)&g_xBC[(m0 + tc + r) * CONVD + h * HD + c4];
            Xs[r][c4 + 0] = BF_LO(raw.x); Xs[r][c4 + 1] = BF_HI(raw.x);
            Xs[r][c4 + 2] = BF_LO(raw.y); Xs[r][c4 + 3] = BF_HI(raw.y);
        }
        for (int i = tid; i < 32 * 16; i += 256) {
            int r = i >> 4, c8 = (i & 15) * 8;
            float w = wts[r];
            uint4 raw = *(const uint4*)&g_xBC[(m0 + tc + r) * CONVD + DIN + c8];
            Bw[r][c8 + 0] = f2tf(w * blo(raw.x));
            Bw[r][c8 + 1] = f2tf(w * bhi(raw.x));
            Bw[r][c8 + 2] = f2tf(w * blo(raw.y));
            Bw[r][c8 + 3] = f2tf(w * bhi(raw.y));
            Bw[r][c8 + 4] = f2tf(w * blo(raw.z));
            Bw[r][c8 + 5] = f2tf(w * bhi(raw.z));
            Bw[r][c8 + 6] = f2tf(w * blo(raw.w));
            Bw[r][c8 + 7] = f2tf(w * bhi(raw.w));
        }
        __syncthreads();
        #pragma unroll
        for (int k8 = 0; k8 < 32; k8 += 8) {
            int rA = wm + (lane >> 2), kA = k8 + (lane & 3);
            uint32_t a0 = Xs[kA][rA],     a1 = Xs[kA][rA + 8];
            uint32_t a2 = Xs[kA + 4][rA], a3 = Xs[kA + 4][rA + 8];
            #pragma unroll
            for (int ni = 0; ni < 8; ni++) {
                int cn = wn + ni * 8 + (lane >> 2);
                mma_tf32(acc[ni], a0, a1, a2, a3, Bw[kA][cn], Bw[kA + 4][cn]);
            }
        }
    }
    int blk = (bb * 16 + c) * 3 + h;
    int gid = lane >> 2, tig = lane & 3;
    #pragma unroll
    for (int ni = 0; ni < 8; ni++) {
        int p0 = wm + gid;
        int n0 = wn + ni * 8 + tig * 2;
        float* dst = &g_states[blk * (HD * DSTATE)];
        dst[p0 * DSTATE + n0]           = acc[ni][0];
        dst[p0 * DSTATE + n0 + 1]       = acc[ni][1];
        dst[(p0 + 8) * DSTATE + n0]     = acc[ni][2];
        dst[(p0 + 8) * DSTATE + n0 + 1] = acc[ni][3];
    }
}

// ============ kernel 7: inter-chunk recurrence ============
__global__ void k_recur() {
    int bxs = blockIdx.x;          // 192
    int slice = bxs & 7;
    int bh = bxs >> 3;
    int bb = bh / 3, h = bh % 3;
    int tid = threadIdx.x;         // 256
    float hr[4] = {0.f, 0.f, 0.f, 0.f};
    for (int c = 0; c < NC; c++) {
        int blk = (bb * 16 + c) * 3 + h;
        float decay = __expf(g_dAc[(bb * LSEQ + c * CHUNK + 255) * NH + h]);
        #pragma unroll
        for (int r = 0; r < 4; r++) {
            int idx = blk * (HD * DSTATE) + slice * 1024 + r * 256 + tid;
            g_prev[idx] = hr[r];
            hr[r] = fmaf(decay, hr[r], g_states[idx]);
        }
    }
}

// ============ kernel 8: inter-chunk y correction via bf16 MMA ============
__global__ void k_ycorr() {
    extern __shared__ uint32_t ysm[];
    uint32_t (*prevS)[68] = (uint32_t(*)[68])ysm;
    uint32_t (*Cs)[68]    = (uint32_t(*)[68])(ysm + 64 * 68);
    float* exps           = (float*)(ysm + 2 * 64 * 68);
    int bx = blockIdx.x;
    int h = bx % 3; int rest = bx / 3;
    int c = rest & 15; int bb = rest >> 4;
    int m0 = bb * LSEQ + c * CHUNK;
    int blk = (bb * 16 + c) * 3 + h;
    int tid = threadIdx.x, lane = tid & 31, wid = tid >> 5;   // 128 thr / 4 warps
    for (int i = tid; i < 64 * 32; i += 128) {
        int p = i >> 5, c4 = (i & 31) * 4;
        float4 v = *(const float4*)&g_prev[blk * (HD * DSTATE) + p * DSTATE + c4];
        prevS[p][(c4 >> 1)]     = packbf(v.x, v.y);
        prevS[p][(c4 >> 1) + 1] = packbf(v.z, v.w);
    }
    int gid = lane >> 2, tig = lane & 3;
    for (int stile = 0; stile < 4; stile++) {
        __syncthreads();
        for (int i = tid; i < 64 * 16; i += 128) {
            int r = i >> 4, q = i & 15;
            uint4 raw = *(const uint4*)&g_xBC[(m0 + stile * 64 + r) * CONVD + (DIN + DSTATE) + q * 8];
            *(uint4*)&Cs[r][q * 4] = raw;
        }
        if (tid < 64) exps[tid] = __expf(g_dAc[(m0 + stile * 64 + tid) * NH + h]);
        __syncthreads();
        float acc[8][4] = {};
        #pragma unroll
        for (int k16 = 0; k16 < 8; k16++) {
            int rA = wid * 16 + gid;
            int kp = k16 * 8 + (lane & 3);
            uint32_t a0 = Cs[rA][kp],     a1 = Cs[rA + 8][kp];
            uint32_t a2 = Cs[rA][kp + 4], a3 = Cs[rA + 8][kp + 4];
            #pragma unroll
            for (int ni = 0; ni < 8; ni++) {
                int cn = ni * 8 + gid;
                mma_bf16(acc[ni], a0, a1, a2, a3, prevS[cn][kp], prevS[cn][kp + 4]);
            }
        }
        #pragma unroll
        for (int ni = 0; ni < 8; ni++) {
            int p = ni * 8 + tig * 2;
            int s0 = wid * 16 + gid;
            int m1 = m0 + stile * 64 + s0;
            int m2 = m1 + 8;
            float eA1 = exps[s0], eA2 = exps[s0 + 8];
            uint32_t y1 = *(uint32_t*)&g_y[m1 * DIN + h * HD + p];
            uint32_t y2 = *(uint32_t*)&g_y[m2 * DIN + h * HD + p];
            float v10 = blo(y1) + eA1 * acc[ni][0];
            float v11 = bhi(y1) + eA1 * acc[ni][1];
            float v20 = blo(y2) + eA2 * acc[ni][2];
            float v21 = bhi(y2) + eA2 * acc[ni][3];
            *(uint32_t*)&g_y[m1 * DIN + h * HD + p] = packbf(v10, v11);
            *(uint32_t*)&g_y[m2 * DIN + h * HD + p] = packbf(v20, v21);
        }
    }
}
#define SMEM_YCORR ((2 * 64 * 68) * 4 + 64 * 4)

// ============ kernel 9: fused gate+rmsnorm+out_proj via bf16 MMA ============
__global__ void k_gateproj(const float* __restrict__ gw, const float* __restrict__ W) {
    extern __shared__ uint32_t gpm[];
    uint32_t (*As)[100] = (uint32_t(*)[100])gpm;
    uint32_t (*Bs)[100] = (uint32_t(*)[100])(gpm + 128 * 100);
    int bm = blockIdx.x * 128;
    int tid = threadIdx.x, lane = tid & 31, wid = tid >> 5;
    for (int i = tid; i < 96 * 48; i += 256) {
        int r = i / 48, q = i - r * 48;
        float4 v = *(const float4*)&W[r * DIN + q * 4];
        Bs[r][q * 2]     = packbf(v.x, v.y);
        Bs[r][q * 2 + 1] = packbf(v.z, v.w);
    }
    int rgrp = lane >> 3, cch = lane & 7;
    int cbase = cch * 4;
    for (int pass = 0; pass < 4; pass++) {
        int row = pass * 32 + wid * 4 + rgrp;
        int m = bm + row;
        float vbuf[24];
        float ss = 0.f;
        #pragma unroll
        for (int j = 0; j < 6; j++) {
            int col = cbase + j * 32;
            uint2 yu = *(const uint2*)&g_y[m * DIN + col];
            uint2 zu = *(const uint2*)&g_zxbcdt[(size_t)m * NPROJ_S + col];
            float y0 = blo(yu.x), y1 = bhi(yu.x);
            float y2 = blo(yu.y), y3 = bhi(yu.y);
            float z0 = blo(zu.x), z1 = bhi(zu.x);
            float z2 = blo(zu.y), z3 = bhi(zu.y);
            float v0 = y0 * (z0 / (1.0f + __expf(-z0)));
            float v1 = y1 * (z1 / (1.0f + __expf(-z1)));
            float v2 = y2 * (z2 / (1.0f + __expf(-z2)));
            float v3 = y3 * (z3 / (1.0f + __expf(-z3)));
            vbuf[j*4+0] = v0; vbuf[j*4+1] = v1; vbuf[j*4+2] = v2; vbuf[j*4+3] = v3;
            ss = fmaf(v0, v0, fmaf(v1, v1, fmaf(v2, v2, fmaf(v3, v3, ss))));
        }
        ss += __shfl_xor_sync(0xffffffffu, ss, 1);
        ss += __shfl_xor_sync(0xffffffffu, ss, 2);
        ss += __shfl_xor_sync(0xffffffffu, ss, 4);
        float rr = rsqrtf(ss / 192.0f + 1e-5f);
        #pragma unroll
        for (int j = 0; j < 6; j++) {
            int col = cbase + j * 32;
            float g0 = gw[col], g1 = gw[col + 1], g2 = gw[col + 2], g3 = gw[col + 3];
            As[row][(col >> 1)]     = packbf(vbuf[j*4+0] * rr * g0, vbuf[j*4+1] * rr * g1);
            As[row][(col >> 1) + 1] = packbf(vbuf[j*4+2] * rr * g2, vbuf[j*4+3] * rr * g3);
        }
    }
    __syncthreads();
    int wm = (wid & 3) * 32;
    int wn = (wid >> 2) * 48;
    float acc[2][6][4] = {};
    #pragma unroll
    for (int k16 = 0; k16 < 12; k16++) {
        int kp = k16 * 8 + (lane & 3);
        uint32_t af[2][4];
        #pragma unroll
        for (int mi = 0; mi < 2; mi++) {
            int r = wm + mi * 16 + (lane >> 2);
            af[mi][0] = As[r][kp];     af[mi][1] = As[r + 8][kp];
            af[mi][2] = As[r][kp + 4]; af[mi][3] = As[r + 8][kp + 4];
        }
        #pragma unroll
        for (int ni = 0; ni < 6; ni++) {
            int cn = wn + ni * 8 + (lane >> 2);
            uint32_t b0 = Bs[cn][kp], b1 = Bs[cn][kp + 4];
            #pragma unroll
            for (int mi = 0; mi < 2; mi++)
                mma_bf16(acc[mi][ni], af[mi][0], af[mi][1], af[mi][2], af[mi][3], b0, b1);
        }
    }
    int gid = lane >> 2, tig = lane & 3;
    #pragma unroll
    for (int mi = 0; mi < 2; mi++) {
        int r0 = bm + wm + mi * 16 + gid;
        #pragma unroll
        for (int ni = 0; ni < 6; ni++) {
            int c0 = wn + ni * 8 + tig * 2;
            *(__nv_bfloat162*)&g_ysd[r0 * CMODEL + c0] =
                __floats2bfloat162_rn(acc[mi][ni][0], acc[mi][ni][1]);
            *(__nv_bfloat162*)&g_ysd[(r0 + 8) * CMODEL + c0] =
                __floats2bfloat162_rn(acc[mi][ni][2], acc[mi][ni][3]);
        }
    }
}
#define SMEM_GATEPROJ ((128 * 100 + 96 * 100) * 4)

// ============ kernel 10: un-scan + residual (16-pixel tiles) ============
__global__ void k_unscan(const float* __restrict__ x, float* __restrict__ out) {
    __shared__ float sy[96][17];
    int bi = blockIdx.x >> 8;
    int l0 = (blockIdx.x & 255) * 16;
    int tid = threadIdx.x;                 // 256
    for (int i = tid; i < 1536; i += 256) {
        int ll = i / 96, ch = i - ll * 96;
        int l = l0 + ll;
        int hh = l >> 6, ww = l & 63;
        int lt = (ww << 6) + hh;
        float v = __bfloat162float(g_ysd[(((bi * 4 + 0) << 12) + l) * 96 + ch])
                + __bfloat162float(g_ysd[(((bi * 4 + 1) << 12) + (4095 - l)) * 96 + ch])
                + __bfloat162float(g_ysd[(((bi * 4 + 2) << 12) + lt) * 96 + ch])
                + __bfloat162float(g_ysd[(((bi * 4 + 3) << 12) + (4095 - lt)) * 96 + ch]);
        sy[ch][ll] = 0.25f * v;
    }
    __syncthreads();
    for (int i = tid; i < 96 * 16; i += 256) {
        int ch = i >> 4, ll = i & 15;
        int idx = ((bi * 96 + ch) << 12) + l0 + ll;
        out[idx] = x[idx] + sy[ch][ll];
    }
}

// ---------------- launch (fork/join stream overlap) ----------------
extern "C" void kernel_launch(void* const* d_in, const int* in_sizes, int n_in,
                              void* d_out, int out_size) {
    const float* x          = (const float*)d_in[0];
    const float* norm_w     = (const float*)d_in[1];
    const float* in_proj_w  = (const float*)d_in[2];
    const float* conv_w     = (const float*)d_in[3];
    const float* conv_b     = (const float*)d_in[4];
    const float* dt_bias    = (const float*)d_in[5];
    const float* A_log      = (const float*)d_in[6];
    const float* Dp         = (const float*)d_in[7];
    const float* gnorm_w    = (const float*)d_in[8];
    const float* out_proj_w = (const float*)d_in[9];
    float* out = (float*)d_out;

    static cudaStream_t sB = 0;
    static cudaEvent_t e1 = 0, e2 = 0, e3 = 0, e4 = 0;
    static int inited = 0;
    if (!inited) {
        cudaFuncSetAttribute(k_inproj_mma, cudaFuncAttributeMaxDynamicSharedMemorySize, SMEM_INPROJ);
        cudaFuncSetAttribute(k_intra_mma, cudaFuncAttributeMaxDynamicSharedMemorySize, SMEM_INTRA);
        cudaFuncSetAttribute(k_ycorr, cudaFuncAttributeMaxDynamicSharedMemorySize, SMEM_YCORR);
        cudaFuncSetAttribute(k_gateproj, cudaFuncAttributeMaxDynamicSharedMemorySize, SMEM_GATEPROJ);
        cudaStreamCreateWithFlags(&sB, cudaStreamNonBlocking);
        cudaEventCreateWithFlags(&e1, cudaEventDisableTiming);
        cudaEventCreateWithFlags(&e2, cudaEventDisableTiming);
        cudaEventCreateWithFlags(&e3, cudaEventDisableTiming);
        cudaEventCreateWithFlags(&e4, cudaEventDisableTiming);
        inited = 1;
    }

    k_rms_scan<<<BATCH * 256, 256>>>(x, norm_w);
    k_inproj_mma<<<dim3(6, MROWS / 128), 256, SMEM_INPROJ>>>(in_proj_w);
    cudaEventRecord(e1, 0);

    cudaStreamWaitEvent(sB, e1, 0);
    k_dt<<<BB * NC, CHUNK, 0, sB>>>(dt_bias, A_log);
    cudaEventRecord(e3, sB);

    k_conv<<<MROWS / 8, 224>>>(conv_w, conv_b);
    cudaEventRecord(e2, 0);

    cudaStreamWaitEvent(sB, e2, 0);
    k_states<<<BB * NC * NH, 256, 0, sB>>>();
    k_recur<<<BB * NH * 8, 256, 0, sB>>>();
    cudaEventRecord(e4, sB);

    cudaStreamWaitEvent(0, e3, 0);
    k_intra_mma<<<BB * NC * NH * 4, 128, SMEM_INTRA>>>(Dp);

    cudaStreamWaitEvent(0, e4, 0);
    k_ycorr<<<BB * NC * NH, 128, SMEM_YCORR>>>();
    k_gateproj<<<MROWS / 128, 256, SMEM_GATEPROJ>>>(gnorm_w, out_proj_w);
    k_unscan<<<BATCH * 256, 256>>>(x, out);
}